// round 11
// baseline (speedup 1.0000x reference)
#include <cuda_runtime.h>

// DfOp: complex order-5 causal FIR on first 96 freq bins, copy the rest.
// spec: (B=8, T=3000, F=481, 2) f32 ; coef: (B=8, T=3000, 96, 10) f32
//
// R11 = R10 champion + evict-first (.cs) hints on STORES ONLY. Output is
// write-once/never-read, so streaming the stores frees L2 capacity and
// write-back bandwidth for the 5x-reused DF tap lines. Loads stay default
// (R5 showed .cs loads hurt tap reuse). Everything else identical to R10.

#define T_DIM 3000
#define F_DIM 481
#define NDF   96
#define NO    5

__global__ __launch_bounds__(256) void df_kernel(
    const float* __restrict__ spec,
    const float* __restrict__ coef,
    float* __restrict__ out)
{
    const int bt = blockIdx.x;          // row = b*T + t
    const int t  = bt % T_DIM;

    const float2* __restrict__ spec2 = reinterpret_cast<const float2*>(spec);
    const float4* __restrict__ spec4 = reinterpret_cast<const float4*>(spec);
    float2* __restrict__ out2 = reinterpret_cast<float2*>(out);
    float4* __restrict__ out4 = reinterpret_cast<float4*>(out);

    const size_t row = (size_t)bt * F_DIM;     // float2 units
    const int tid = threadIdx.x;

    if (tid < NDF) {
        // ---- DF path: one bin per thread ----
        const int f = tid;
        const float2* __restrict__ c2 =
            reinterpret_cast<const float2*>(coef + ((size_t)bt * NDF + f) * (2 * NO));

        // Batch 1: coefficient loads (unpredicated, independent).
        const float2 p0 = c2[0];
        const float2 p1 = c2[1];
        const float2 p2 = c2[2];
        const float2 p3 = c2[3];
        const float2 p4 = c2[4];

        // Batch 2: tap loads, block-uniform fast path (t>=4 for 99.87% of rows).
        float2 x[NO];
        if (t >= NO - 1) {
            #pragma unroll
            for (int k = 0; k < NO; ++k)
                x[k] = spec2[((size_t)(bt - (NO - 1) + k)) * F_DIM + f];
        } else {
            #pragma unroll
            for (int k = 0; k < NO; ++k) {
                x[k] = make_float2(0.f, 0.f);
                if (t - (NO - 1) + k >= 0)
                    x[k] = spec2[((size_t)(bt - (NO - 1) + k)) * F_DIM + f];
            }
        }

        const float cr[NO] = {p0.x, p0.y, p1.x, p1.y, p2.x};
        const float ci[NO] = {p2.y, p3.x, p3.y, p4.x, p4.y};

        float fr = 0.f, fi = 0.f;
        #pragma unroll
        for (int k = 0; k < NO; ++k) {
            fr += x[k].x * cr[k] - x[k].y * ci[k];
            fi += x[k].x * ci[k] + x[k].y * cr[k];
        }
        __stcs(out2 + (row + f), make_float2(fr, fi));
    } else {
        // ---- Copy path: bins [96,481) = 192 float4 + 1 float2 per row ----
        const int ct = tid - NDF;                  // 0..159
        const bool odd = (bt & 1);
        const size_t v4base = (row + NDF + (odd ? 1 : 0)) >> 1;

        {
            const size_t i4 = v4base + ct;
            __stcs(out4 + i4, spec4[i4]);
        }
        if (ct < 32) {
            const size_t i4 = v4base + 160 + ct;
            __stcs(out4 + i4, spec4[i4]);
        }
        if (ct == 32) {
            const size_t i2 = row + (odd ? NDF : (F_DIM - 1));
            __stcs(out2 + i2, spec2[i2]);
        }
    }
}

extern "C" void kernel_launch(void* const* d_in, const int* in_sizes, int n_in,
                              void* d_out, int out_size)
{
    const float* spec = (const float*)d_in[0];
    const float* coef = (const float*)d_in[1];
    float* out        = (float*)d_out;

    df_kernel<<<8 * T_DIM, 256>>>(spec, coef, out);
}

// round 12
// speedup vs baseline: 1.0007x; 1.0007x over previous
#include <cuda_runtime.h>

// DfOp: complex order-5 causal FIR on first 96 freq bins, copy the rest.
// spec: (B=8, T=3000, F=481, 2) f32 ; coef: (B=8, T=3000, 96, 10) f32
//
// FINAL (champion, R4/R10 lineage): one block per (b,t) row; threads 0..95
// compute one DF bin each (5x coef LDG.64 + 5x tap LDG.64 front-batched,
// block-uniform t>=4 fast path); threads 96..255 copy bins [96,481) with
// row-parity-uniform float4 accesses.
//
// Why this shape is final: the kernel is DRAM-compulsory-bound (~245-277 MB
// at ~6.4 TB/s counter / ~7.2 TB/s effective). Ten structural variants
// (pair-per-thread, flat work queues, row fusion, split populations, parity
// pairing, cache hints, issue reordering) were benched; everything that
// reduced thread-level parallelism or added divergence regressed 10-35%,
// everything else was noise-neutral. 49.9 us (R1) -> 43.5 us here.

#define T_DIM 3000
#define F_DIM 481
#define NDF   96
#define NO    5

__global__ __launch_bounds__(256) void df_kernel(
    const float* __restrict__ spec,
    const float* __restrict__ coef,
    float* __restrict__ out)
{
    const int bt = blockIdx.x;          // row = b*T + t
    const int t  = bt % T_DIM;

    const float2* __restrict__ spec2 = reinterpret_cast<const float2*>(spec);
    const float4* __restrict__ spec4 = reinterpret_cast<const float4*>(spec);
    float2* __restrict__ out2 = reinterpret_cast<float2*>(out);
    float4* __restrict__ out4 = reinterpret_cast<float4*>(out);

    const size_t row = (size_t)bt * F_DIM;     // float2 units
    const int tid = threadIdx.x;

    if (tid < NDF) {
        // ---- DF path: one bin per thread ----
        const int f = tid;
        const float2* __restrict__ c2 =
            reinterpret_cast<const float2*>(coef + ((size_t)bt * NDF + f) * (2 * NO));

        // Batch 1: coefficient loads (unpredicated, independent).
        const float2 p0 = c2[0];
        const float2 p1 = c2[1];
        const float2 p2 = c2[2];
        const float2 p3 = c2[3];
        const float2 p4 = c2[4];

        // Batch 2: tap loads, block-uniform fast path (t>=4 for 99.87% of rows).
        float2 x[NO];
        if (t >= NO - 1) {
            #pragma unroll
            for (int k = 0; k < NO; ++k)
                x[k] = spec2[((size_t)(bt - (NO - 1) + k)) * F_DIM + f];
        } else {
            #pragma unroll
            for (int k = 0; k < NO; ++k) {
                x[k] = make_float2(0.f, 0.f);
                if (t - (NO - 1) + k >= 0)
                    x[k] = spec2[((size_t)(bt - (NO - 1) + k)) * F_DIM + f];
            }
        }

        // Math only after all loads are in flight.
        const float cr[NO] = {p0.x, p0.y, p1.x, p1.y, p2.x};
        const float ci[NO] = {p2.y, p3.x, p3.y, p4.x, p4.y};

        float fr = 0.f, fi = 0.f;
        #pragma unroll
        for (int k = 0; k < NO; ++k) {
            fr += x[k].x * cr[k] - x[k].y * ci[k];
            fi += x[k].x * ci[k] + x[k].y * cr[k];
        }
        out2[row + f] = make_float2(fr, fi);
    } else {
        // ---- Copy path: bins [96,481) = 192 float4 + 1 float2 per row ----
        const int ct = tid - NDF;                  // 0..159
        const bool odd = (bt & 1);
        const size_t v4base = (row + NDF + (odd ? 1 : 0)) >> 1;

        {
            const size_t i4 = v4base + ct;
            out4[i4] = spec4[i4];
        }
        if (ct < 32) {
            const size_t i4 = v4base + 160 + ct;
            out4[i4] = spec4[i4];
        }
        if (ct == 32) {
            const size_t i2 = row + (odd ? NDF : (F_DIM - 1));
            out2[i2] = spec2[i2];
        }
    }
}

extern "C" void kernel_launch(void* const* d_in, const int* in_sizes, int n_in,
                              void* d_out, int out_size)
{
    const float* spec = (const float*)d_in[0];
    const float* coef = (const float*)d_in[1];
    float* out        = (float*)d_out;

    df_kernel<<<8 * T_DIM, 256>>>(spec, coef, out);
}